// round 10
// baseline (speedup 1.0000x reference)
#include <cuda_runtime.h>
#include <cstdint>

#define NN 100000
#define NE 3200000
#define H  32

typedef unsigned long long ull;

// __device__ scratch (no allocations allowed)
__device__ float4 g_L1q[H];                       // (A,B,C,0): h1 = relu(A*n + B*t + C)
__device__ __align__(16) float4 g_sums4[NN];      // xyz = sums, w = count

// ---- packed f32x2 helpers (ptxas will not auto-fuse these) ----
__device__ __forceinline__ ull ffma2(ull a, ull b, ull c) {
    ull d;
    asm("fma.rn.f32x2 %0, %1, %2, %3;" : "=l"(d) : "l"(a), "l"(b), "l"(c));
    return d;
}
__device__ __forceinline__ ull fmul2(ull a, ull b) {
    ull d;
    asm("mul.rn.f32x2 %0, %1, %2;" : "=l"(d) : "l"(a), "l"(b));
    return d;
}
__device__ __forceinline__ ull fadd2(ull a, ull b) {
    ull d;
    asm("add.rn.f32x2 %0, %1, %2;" : "=l"(d) : "l"(a), "l"(b));
    return d;
}
__device__ __forceinline__ ull pack2(float lo, float hi) {
    ull r;
    asm("mov.b64 %0, {%1, %2};" : "=l"(r) : "f"(lo), "f"(hi));
    return r;
}
__device__ __forceinline__ float2 unpack2(ull v) {
    float2 f;
    asm("mov.b64 {%0, %1}, %2;" : "=f"(f.x), "=f"(f.y) : "l"(v));
    return f;
}
__device__ __forceinline__ ull relu2(ull v) {
    float2 f = unpack2(v);
    return pack2(fmaxf(f.x, 0.0f), fmaxf(f.y, 0.0f));
}
// one vector reduction: (+u0,+u1,+u2,+1.0) onto a float4 cell
__device__ __forceinline__ void red_add_v4(float4* p, float u0, float u1, float u2) {
    asm volatile("red.global.add.v4.f32 [%0], {%1, %2, %3, %4};"
                 :: "l"(p), "f"(u0), "f"(u1), "f"(u2), "f"(1.0f) : "memory");
}

// ---------------------------------------------------------------------------
__global__ void prep_kernel(const float* __restrict__ W1,
                            const float* __restrict__ gamma,
                            const float* __restrict__ beta,
                            const float* __restrict__ mean,
                            const float* __restrict__ var) {
    int k = threadIdx.x;
    if (k < H) {
        float s = gamma[k] * rsqrtf(var[k] + 1e-5f);
        g_L1q[k] = make_float4(W1[k] * s, W1[H + k] * s, beta[k] - mean[k] * s, 0.0f);
    }
}

__global__ void zero_kernel() {
    int i = blockIdx.x * blockDim.x + threadIdx.x;
    if (i < NN) g_sums4[i] = make_float4(0.0f, 0.0f, 0.0f, 0.0f);
}

// ---------------------------------------------------------------------------
// TWO edges per thread; weight rows loaded once per pair. Accumulators are
// ReLU'd IN PLACE and reused as h2 (keeps peak live regs < 128 => no spills).
__global__ void __launch_bounds__(256, 2) edge_kernel(
    const float* __restrict__ x,
    const int* __restrict__ ei,
    const float* __restrict__ W2, const float* __restrict__ b2,
    const float* __restrict__ W3, const float* __restrict__ b3,
    const float* __restrict__ W4,
    const float* __restrict__ W5, const float* __restrict__ b5,
    float* __restrict__ out_m)
{
    __shared__ __align__(16) float sW2[H * H];    // row-major [j][k]
    __shared__ __align__(16) float sW3T[H * H];   // transposed [k][j]
    __shared__ __align__(16) float4 sL1[H];
    __shared__ __align__(16) float sb2[H], sb3[H], sW4[H], sW5[H];
    __shared__ float sb5v;

    int tid = threadIdx.x;
    for (int t = tid; t < H * H; t += 256) {
        sW2[t] = W2[t];
        int k = t >> 5, j = t & 31;
        sW3T[t] = W3[j * H + k];
    }
    if (tid < H) {
        sL1[tid] = g_L1q[tid];
        sb2[tid] = b2[tid];
        sb3[tid] = b3[tid];
        sW4[tid] = W4[tid];
        sW5[tid] = W5[tid];
    }
    if (tid == 0) sb5v = b5[0];
    __syncthreads();

    long e0 = ((long)blockIdx.x * 256 + tid) * 2;
    long e1 = e0 + 1;

    int2 di = *(const int2*)(ei + e0);
    int2 sj = *(const int2*)(ei + (long)NE + e0);
    int ia = di.x, ib = di.y, ja = sj.x, jb = sj.y;
    if ((unsigned)ia >= NN || (unsigned)ib >= NN ||
        (unsigned)ja >= NN || (unsigned)jb >= NN) return;

    float xa0 = __ldg(&x[3 * ia + 0]), xa1 = __ldg(&x[3 * ia + 1]), xa2 = __ldg(&x[3 * ia + 2]);
    float ya0 = __ldg(&x[3 * ja + 0]), ya1 = __ldg(&x[3 * ja + 1]), ya2 = __ldg(&x[3 * ja + 2]);
    float xb0 = __ldg(&x[3 * ib + 0]), xb1 = __ldg(&x[3 * ib + 1]), xb2 = __ldg(&x[3 * ib + 2]);
    float yb0 = __ldg(&x[3 * jb + 0]), yb1 = __ldg(&x[3 * jb + 1]), yb2 = __ldg(&x[3 * jb + 2]);

    float da0 = xa0 - ya0, da1 = xa1 - ya1, da2 = xa2 - ya2;
    float db0 = xb0 - yb0, db1 = xb1 - yb1, db2 = xb2 - yb2;
    float nsq_a = da0 * da0 + da1 * da1 + da2 * da2;
    float nsq_b = db0 * db0 + db1 * db1 + db2 * db2;
    float dot_a = xa0 * ya0 + xa1 * ya1 + xa2 * ya2;
    float dot_b = xb0 * yb0 + xb1 * yb1 + xb2 * yb2;

    float na = log1pf(nsq_a);
    float nb = log1pf(nsq_b);
    float ta = copysignf(log1pf(fabsf(dot_a)), dot_a);
    float tb = copysignf(log1pf(fabsf(dot_b)), dot_b);

    // ---- fused layer1 + layer2 ----
    ull acc_a[H / 2], acc_b[H / 2];
    {
        const ull* b2p = (const ull*)sb2;
#pragma unroll
        for (int q = 0; q < H / 2; q++) { acc_a[q] = b2p[q]; acc_b[q] = b2p[q]; }
    }
#pragma unroll 2
    for (int j = 0; j < H; j++) {
        float4 c = sL1[j];
        float ha = fmaxf(fmaf(na, c.x, fmaf(ta, c.y, c.z)), 0.0f);
        float hb = fmaxf(fmaf(nb, c.x, fmaf(tb, c.y, c.z)), 0.0f);
        ull hap = pack2(ha, ha);
        ull hbp = pack2(hb, hb);
        const ulonglong2* row = (const ulonglong2*)(sW2 + j * H);
#pragma unroll
        for (int q = 0; q < H / 4; q++) {
            ulonglong2 w = row[q];                 // one load, two edges
            acc_a[2 * q + 0] = ffma2(hap, w.x, acc_a[2 * q + 0]);
            acc_a[2 * q + 1] = ffma2(hap, w.y, acc_a[2 * q + 1]);
            acc_b[2 * q + 0] = ffma2(hbp, w.x, acc_b[2 * q + 0]);
            acc_b[2 * q + 1] = ffma2(hbp, w.y, acc_b[2 * q + 1]);
        }
    }

    // ---- h2 = relu(acc) IN PLACE (acc_* IS h2 from here on) ----
#pragma unroll
    for (int q = 0; q < H / 2; q++) { acc_a[q] = relu2(acc_a[q]); acc_b[q] = relu2(acc_b[q]); }

    // ---- gate: wgt = sigmoid(h2 . W5 + b5) ----
    float wgt_a, wgt_b;
    {
        const ull* w5p = (const ull*)sW5;
        ull za0 = 0, za1 = 0, zb0 = 0, zb1 = 0;
#pragma unroll
        for (int q = 0; q < H / 2; q += 2) {
            za0 = ffma2(acc_a[q], w5p[q], za0);
            za1 = ffma2(acc_a[q + 1], w5p[q + 1], za1);
            zb0 = ffma2(acc_b[q], w5p[q], zb0);
            zb1 = ffma2(acc_b[q + 1], w5p[q + 1], zb1);
        }
        float2 fa = unpack2(fadd2(za0, za1));
        float2 fb = unpack2(fadd2(zb0, zb1));
        wgt_a = 1.0f / (1.0f + expf(-(fa.x + fa.y + sb5v)));
        wgt_b = 1.0f / (1.0f + expf(-(fb.x + fb.y + sb5v)));
    }

    // ---- m = h2 * wgt, write out ----
    {
        ull wpa = pack2(wgt_a, wgt_a);
        ull wpb = pack2(wgt_b, wgt_b);
        ulonglong2* moa = (ulonglong2*)(out_m + e0 * H);
        ulonglong2* mob = (ulonglong2*)(out_m + e1 * H);
#pragma unroll
        for (int q = 0; q < H / 4; q++) {
            ulonglong2 va, vb;
            va.x = fmul2(acc_a[2 * q + 0], wpa);
            va.y = fmul2(acc_a[2 * q + 1], wpa);
            vb.x = fmul2(acc_b[2 * q + 0], wpb);
            vb.y = fmul2(acc_b[2 * q + 1], wpb);
            moa[q] = va;
            mob[q] = vb;
        }
    }

    // ---- phi_x, k-outer vs transposed W3; rows shared by both edges ----
    float phix_a0 = 0.0f, phix_a1 = 0.0f, phix_b0 = 0.0f, phix_b1 = 0.0f;
#pragma unroll 2
    for (int k = 0; k < H; k++) {
        const ulonglong2* row = (const ulonglong2*)(sW3T + k * H);
        ull sa0 = 0, sa1 = 0, sb0 = 0, sb1 = 0;
#pragma unroll
        for (int q = 0; q < H / 4; q++) {
            ulonglong2 w = row[q];                 // one load, two edges
            sa0 = ffma2(acc_a[2 * q + 0], w.x, sa0);
            sa1 = ffma2(acc_a[2 * q + 1], w.y, sa1);
            sb0 = ffma2(acc_b[2 * q + 0], w.x, sb0);
            sb1 = ffma2(acc_b[2 * q + 1], w.y, sb1);
        }
        float2 fa = unpack2(fadd2(sa0, sa1));
        float2 fb = unpack2(fadd2(sb0, sb1));
        float a3a = fa.x + fa.y;
        float a3b = fb.x + fb.y;
        float b3k = sb3[k], w4k = sW4[k];
        float ua = fmaxf(fmaf(wgt_a, a3a, b3k), 0.0f);
        float ub = fmaxf(fmaf(wgt_b, a3b, b3k), 0.0f);
        if (k & 1) { phix_a1 = fmaf(ua, w4k, phix_a1); phix_b1 = fmaf(ub, w4k, phix_b1); }
        else       { phix_a0 = fmaf(ua, w4k, phix_a0); phix_b0 = fmaf(ub, w4k, phix_b0); }
    }
    float phix_a = phix_a0 + phix_a1;
    float phix_b = phix_b0 + phix_b1;

    // ---- scatter-mean: ONE vector reduction per edge ----
    float ua0 = fminf(fmaxf(da0 * phix_a, -100.0f), 100.0f);
    float ua1 = fminf(fmaxf(da1 * phix_a, -100.0f), 100.0f);
    float ua2 = fminf(fmaxf(da2 * phix_a, -100.0f), 100.0f);
    float ub0 = fminf(fmaxf(db0 * phix_b, -100.0f), 100.0f);
    float ub1 = fminf(fmaxf(db1 * phix_b, -100.0f), 100.0f);
    float ub2 = fminf(fmaxf(db2 * phix_b, -100.0f), 100.0f);
    red_add_v4(&g_sums4[ia], ua0, ua1, ua2);
    red_add_v4(&g_sums4[ib], ub0, ub1, ub2);
}

// ---------------------------------------------------------------------------
__global__ void node_kernel(const float* __restrict__ x, float* __restrict__ out_x) {
    int n = blockIdx.x * blockDim.x + threadIdx.x;
    if (n < NN) {
        float4 s = g_sums4[n];
        float inv = 1.0f / fmaxf(s.w, 1.0f);
        out_x[3 * n + 0] = x[3 * n + 0] + s.x * inv;
        out_x[3 * n + 1] = x[3 * n + 1] + s.y * inv;
        out_x[3 * n + 2] = x[3 * n + 2] + s.z * inv;
    }
}

// ---------------------------------------------------------------------------
extern "C" void kernel_launch(void* const* d_in, const int* in_sizes, int n_in,
                              void* d_out, int out_size) {
    const float* x   = (const float*)d_in[0];
    const int*   ei  = (const int*)d_in[1];     // int32 (jax default x64-disabled)
    const float* W1  = (const float*)d_in[2];
    const float* gma = (const float*)d_in[3];
    const float* bta = (const float*)d_in[4];
    const float* mea = (const float*)d_in[5];
    const float* var = (const float*)d_in[6];
    const float* W2  = (const float*)d_in[7];
    const float* b2  = (const float*)d_in[8];
    const float* W3  = (const float*)d_in[9];
    const float* b3  = (const float*)d_in[10];
    const float* W4  = (const float*)d_in[11];
    const float* W5  = (const float*)d_in[12];
    const float* b5  = (const float*)d_in[13];

    float* out_x = (float*)d_out;          // x_tilde: [NN, 3]
    float* out_m = out_x + (long)NN * 3;   // m: [NE, H]

    zero_kernel<<<(NN + 255) / 256, 256>>>();
    prep_kernel<<<1, 32>>>(W1, gma, bta, mea, var);
    edge_kernel<<<NE / 512, 256>>>(x, ei, W2, b2, W3, b3, W4, W5, b5, out_m);  // 2 edges/thread
    node_kernel<<<(NN + 255) / 256, 256>>>(x, out_x);
}